// round 3
// baseline (speedup 1.0000x reference)
#include <cuda_runtime.h>
#include <math.h>

#define NMAX 50000
#define EMAX 800000
#define GNUM 64
#define EPSV 1e-5f
#define FINF 3.402823466e38f

// ---------------- scratch (device globals; no allocation allowed) ----------------
// All arrays force-aligned to 256B: several are accessed through float4*/float2*
// casts and a bare __device__ float[] only guarantees 4B alignment (misaligned
// LDG.128 traps err716).
__device__ __align__(256) float g_A[NMAX * 64];        // c_i = x@Wi^T + pre_b
__device__ __align__(256) float g_B[NMAX * 64];        // x@Wj^T
__device__ __align__(256) float g_aggr[NMAX * 256];    // [mean | min | max | std]
__device__ __align__(256) float g_t[NMAX * 64];        // post output
__device__ __align__(256) float g_x1[NMAX * 64];       // ping-pong features
__device__ __align__(256) float g_x2[NMAX * 64];
__device__ __align__(256) float g_scal[NMAX * 2];      // amp, att per node
__device__ __align__(256) int   g_deg[NMAX];
__device__ __align__(256) int   g_off[NMAX + 1];
__device__ __align__(256) int   g_cursor[NMAX];
__device__ __align__(256) int   g_srcs[EMAX];
__device__ __align__(256) int   g_scan[NMAX];
__device__ __align__(256) int   g_blk[64];
__device__ __align__(256) float g_stat[1];             // sum of log(deg+1)
__device__ __align__(256) float g_pool[GNUM * 64];
__device__ __align__(256) float g_cnt[GNUM];

__device__ __forceinline__ const float* sel_in(int sel, const float* ext) {
    return sel == 0 ? ext : (sel == 1 ? (const float*)g_x1 : (const float*)g_x2);
}

// ---------------- setup kernels ----------------
__global__ void k_zero(int n) {
    int i = blockIdx.x * blockDim.x + threadIdx.x;
    if (i < n) { g_deg[i] = 0; g_cursor[i] = 0; }
    if (i < GNUM * 64) g_pool[i] = 0.f;
    if (i < GNUM) g_cnt[i] = 0.f;
    if (i == 0) { g_stat[0] = 0.f; g_off[0] = 0; }
}

__global__ void k_deg(const int* __restrict__ ei, int E) {
    int e = blockIdx.x * blockDim.x + threadIdx.x;
    if (e >= E) return;
    atomicAdd(&g_deg[ei[E + e]], 1);
}

__global__ void k_scan1(int n) {
    __shared__ int sh[1024];
    int i = blockIdx.x * 1024 + threadIdx.x;
    int v = (i < n) ? g_deg[i] : 0;
    sh[threadIdx.x] = v;
    __syncthreads();
    for (int s = 1; s < 1024; s <<= 1) {
        int t = (threadIdx.x >= s) ? sh[threadIdx.x - s] : 0;
        __syncthreads();
        sh[threadIdx.x] += t;
        __syncthreads();
    }
    if (i < n) g_scan[i] = sh[threadIdx.x];
    if (threadIdx.x == 1023 && blockIdx.x < 64) g_blk[blockIdx.x] = sh[1023];
}

__global__ void k_scan2(int nb) {
    if (threadIdx.x == 0 && blockIdx.x == 0) {
        int run = 0;
        if (nb > 64) nb = 64;
        for (int b = 0; b < nb; b++) { int t = g_blk[b]; g_blk[b] = run; run += t; }
    }
}

__global__ void k_scan3(int n) {
    int i = blockIdx.x * 1024 + threadIdx.x;
    if (i < n) g_off[i + 1] = g_scan[i] + g_blk[blockIdx.x];
}

__global__ void k_csr(const int* __restrict__ ei, int E) {
    int e = blockIdx.x * blockDim.x + threadIdx.x;
    if (e >= E) return;
    int s = ei[e], d = ei[E + e];
    int pos = g_off[d] + atomicAdd(&g_cursor[d], 1);
    g_srcs[pos] = s;
}

__global__ void k_stat(int n) {
    int i = blockIdx.x * blockDim.x + threadIdx.x;
    float v = (i < n) ? logf((float)g_deg[i] + 1.f) : 0.f;
#pragma unroll
    for (int s = 16; s; s >>= 1) v += __shfl_down_sync(0xffffffffu, v, s);
    __shared__ float sh[32];
    if ((threadIdx.x & 31) == 0) sh[threadIdx.x >> 5] = v;
    __syncthreads();
    if (threadIdx.x < 32) {
        float t = (threadIdx.x < (blockDim.x >> 5)) ? sh[threadIdx.x] : 0.f;
#pragma unroll
        for (int s = 16; s; s >>= 1) t += __shfl_down_sync(0xffffffffu, t, s);
        if (threadIdx.x == 0) atomicAdd(g_stat, t);
    }
}

// ---------------- pre GEMM: A = x@Wi^T + b, B = x@Wj^T ----------------
// 128 threads: thread owns 1 output (64 A outs + 64 B outs), weights in regs.
__global__ __launch_bounds__(128) void k_pre(int insel, const float* __restrict__ ext,
                                             const float* __restrict__ W,
                                             const float* __restrict__ bias, int n) {
    const float* x = sel_in(insel, ext);
    __shared__ float4 xs[32][16];
    int tid = threadIdx.x;
    int o = tid & 63, half = tid >> 6;
    const float* wr = W + o * 128 + half * 64;
    float w[64];
#pragma unroll
    for (int d = 0; d < 64; d++) w[d] = __ldg(wr + d);
    float bv = half ? 0.f : __ldg(bias + o);
    int n0 = blockIdx.x * 32;
#pragma unroll
    for (int i = tid; i < 512; i += 128) {
        int r = i >> 4, c = i & 15, node = n0 + r;
        xs[r][c] = (node < n) ? ((const float4*)x)[node * 16 + c] : make_float4(0.f, 0.f, 0.f, 0.f);
    }
    __syncthreads();
    int lim = min(32, n - n0);
    float* dst = half ? g_B : g_A;
    for (int node = 0; node < lim; node++) {
        float acc = bv;
#pragma unroll
        for (int c = 0; c < 16; c++) {
            float4 v = xs[node][c];
            acc = fmaf(w[4 * c + 0], v.x, acc);
            acc = fmaf(w[4 * c + 1], v.y, acc);
            acc = fmaf(w[4 * c + 2], v.z, acc);
            acc = fmaf(w[4 * c + 3], v.w, acc);
        }
        dst[(n0 + node) * 64 + o] = acc;
    }
}

// ---------------- aggregation: warp per node over CSR ----------------
__global__ __launch_bounds__(256) void k_aggr(int n) {
    int warp = (blockIdx.x * blockDim.x + threadIdx.x) >> 5;
    int lane = threadIdx.x & 31;
    if (warp >= n) return;
    int s = g_off[warp], e = g_off[warp + 1];
    const float2* B2 = (const float2*)g_B;
    float sx = 0.f, sy = 0.f, qx = 0.f, qy = 0.f;
    float mnx = FINF, mny = FINF, mxx = -FINF, mxy = -FINF;
    int i = s;
    for (; i + 4 <= e; i += 4) {
        int a0 = g_srcs[i], a1 = g_srcs[i + 1], a2 = g_srcs[i + 2], a3 = g_srcs[i + 3];
        float2 v0 = B2[a0 * 32 + lane];
        float2 v1 = B2[a1 * 32 + lane];
        float2 v2 = B2[a2 * 32 + lane];
        float2 v3 = B2[a3 * 32 + lane];
        sx += v0.x; sy += v0.y; qx = fmaf(v0.x, v0.x, qx); qy = fmaf(v0.y, v0.y, qy);
        mnx = fminf(mnx, v0.x); mny = fminf(mny, v0.y); mxx = fmaxf(mxx, v0.x); mxy = fmaxf(mxy, v0.y);
        sx += v1.x; sy += v1.y; qx = fmaf(v1.x, v1.x, qx); qy = fmaf(v1.y, v1.y, qy);
        mnx = fminf(mnx, v1.x); mny = fminf(mny, v1.y); mxx = fmaxf(mxx, v1.x); mxy = fmaxf(mxy, v1.y);
        sx += v2.x; sy += v2.y; qx = fmaf(v2.x, v2.x, qx); qy = fmaf(v2.y, v2.y, qy);
        mnx = fminf(mnx, v2.x); mny = fminf(mny, v2.y); mxx = fmaxf(mxx, v2.x); mxy = fmaxf(mxy, v2.y);
        sx += v3.x; sy += v3.y; qx = fmaf(v3.x, v3.x, qx); qy = fmaf(v3.y, v3.y, qy);
        mnx = fminf(mnx, v3.x); mny = fminf(mny, v3.y); mxx = fmaxf(mxx, v3.x); mxy = fmaxf(mxy, v3.y);
    }
    for (; i < e; i++) {
        int a = g_srcs[i];
        float2 v = B2[a * 32 + lane];
        sx += v.x; sy += v.y; qx = fmaf(v.x, v.x, qx); qy = fmaf(v.y, v.y, qy);
        mnx = fminf(mnx, v.x); mny = fminf(mny, v.y); mxx = fmaxf(mxx, v.x); mxy = fmaxf(mxy, v.y);
    }
    int d = e - s;
    float df = (float)d;
    float degv = (float)max(d, 1);
    float2 c = ((const float2*)g_A)[warp * 32 + lane];
    float S1x = fmaf(df, c.x, sx), S1y = fmaf(df, c.y, sy);
    float S2x = df * c.x * c.x + 2.f * c.x * sx + qx;
    float S2y = df * c.y * c.y + 2.f * c.y * sy + qy;
    float meanx = S1x / degv, meany = S1y / degv;
    float varx = fmaxf(S2x / degv - meanx * meanx, 0.f);
    float vary = fmaxf(S2y / degv - meany * meany, 0.f);
    float stdx = sqrtf(varx + EPSV), stdy = sqrtf(vary + EPSV);
    float mnvx, mnvy, mxvx, mxvy;
    if (d > 0) { mnvx = c.x + mnx; mnvy = c.y + mny; mxvx = c.x + mxx; mxvy = c.y + mxy; }
    else { mnvx = mnvy = mxvx = mxvy = 0.f; }
    float2* out = (float2*)(g_aggr + warp * 256);
    out[lane]       = make_float2(meanx, meany);
    out[32 + lane]  = make_float2(mnvx, mnvy);
    out[64 + lane]  = make_float2(mxvx, mxvy);
    out[96 + lane]  = make_float2(stdx, stdy);
    if (lane == 0) {
        float avg = g_stat[0] / (float)n;
        float ld = logf(degv + 1.f);
        g_scal[2 * warp] = ld / avg;
        g_scal[2 * warp + 1] = avg / ld;
    }
}

// ---------------- post GEMM: out[N,64] = virt[N,832] @ W^T + b ----------------
// virt = [x | aggr | amp*aggr | att*aggr]; BM=128, BN=64, BK=32, 256 threads, 8x4 tiles
__global__ __launch_bounds__(256) void k_post(int insel, const float* __restrict__ ext,
                                              const float* __restrict__ W,
                                              const float* __restrict__ bias, int n) {
    const float* x = sel_in(insel, ext);
    __shared__ float As[32][132];
    __shared__ float Ws[32][64];
    int tid = threadIdx.x;
    int tx = tid & 15, ty = tid >> 4;
    int bm = blockIdx.x * 128;
    float acc[8][4];
#pragma unroll
    for (int ii = 0; ii < 8; ii++)
#pragma unroll
        for (int jj = 0; jj < 4; jj++) acc[ii][jj] = 0.f;

    for (int k0 = 0; k0 < 832; k0 += 32) {
        // load A tile (virtual concat gather); each k-chunk is in exactly one section
#pragma unroll
        for (int p = 0; p < 4; p++) {
            int row = p * 32 + (tid >> 3);
            int c4 = (tid & 7) * 4;
            int nn = bm + row;
            float4 v = make_float4(0.f, 0.f, 0.f, 0.f);
            float sc = 1.f;
            if (nn < n) {
                if (k0 < 64) {
                    v = *(const float4*)(x + nn * 64 + k0 + c4);
                } else {
                    int koff = (k0 < 320) ? (k0 - 64) : ((k0 < 576) ? (k0 - 320) : (k0 - 576));
                    v = *(const float4*)(g_aggr + nn * 256 + koff + c4);
                    if (k0 >= 320) sc = __ldg(g_scal + 2 * nn + ((k0 < 576) ? 0 : 1));
                }
            }
            As[c4 + 0][row] = v.x * sc;
            As[c4 + 1][row] = v.y * sc;
            As[c4 + 2][row] = v.z * sc;
            As[c4 + 3][row] = v.w * sc;
        }
        // load W tile
        {
            int o = tid & 63, kk = (tid >> 6) * 8;
            const float* wp = W + o * 832 + k0 + kk;
            float4 a = __ldg((const float4*)wp);
            float4 b2 = __ldg((const float4*)(wp + 4));
            Ws[kk + 0][o] = a.x;  Ws[kk + 1][o] = a.y;
            Ws[kk + 2][o] = a.z;  Ws[kk + 3][o] = a.w;
            Ws[kk + 4][o] = b2.x; Ws[kk + 5][o] = b2.y;
            Ws[kk + 6][o] = b2.z; Ws[kk + 7][o] = b2.w;
        }
        __syncthreads();
#pragma unroll
        for (int k = 0; k < 32; k++) {
            float4 wv = *(const float4*)&Ws[k][tx * 4];
            float4 a0 = *(const float4*)&As[k][ty * 8];
            float4 a1 = *(const float4*)&As[k][ty * 8 + 4];
            float av[8] = {a0.x, a0.y, a0.z, a0.w, a1.x, a1.y, a1.z, a1.w};
            float wl[4] = {wv.x, wv.y, wv.z, wv.w};
#pragma unroll
            for (int ii = 0; ii < 8; ii++)
#pragma unroll
                for (int jj = 0; jj < 4; jj++)
                    acc[ii][jj] = fmaf(av[ii], wl[jj], acc[ii][jj]);
        }
        __syncthreads();
    }
    float4 bv = __ldg((const float4*)(bias + tx * 4));
#pragma unroll
    for (int ii = 0; ii < 8; ii++) {
        int nn = bm + ty * 8 + ii;
        if (nn < n) {
            float4 o;
            o.x = acc[ii][0] + bv.x;
            o.y = acc[ii][1] + bv.y;
            o.z = acc[ii][2] + bv.z;
            o.w = acc[ii][3] + bv.w;
            *(float4*)(g_t + nn * 64 + tx * 4) = o;
        }
    }
}

// ---------------- lin GEMM + relu: x' = relu(t @ lin_w^T + b) ----------------
__global__ __launch_bounds__(128) void k_lin(const float* __restrict__ W,
                                             const float* __restrict__ bias,
                                             int outsel, int n) {
    float* xo = (outsel == 1) ? g_x1 : g_x2;
    __shared__ float4 ts[32][16];
    int tid = threadIdx.x;
    int o = tid & 63, grp = tid >> 6;
    const float* wr = W + o * 64;
    float w[64];
#pragma unroll
    for (int d = 0; d < 64; d++) w[d] = __ldg(wr + d);
    float bv = __ldg(bias + o);
    int n0 = blockIdx.x * 32;
#pragma unroll
    for (int i = tid; i < 512; i += 128) {
        int r = i >> 4, c = i & 15, node = n0 + r;
        ts[r][c] = (node < n) ? ((const float4*)g_t)[node * 16 + c] : make_float4(0.f, 0.f, 0.f, 0.f);
    }
    __syncthreads();
    int lim = min(32, n - n0);
    for (int node = grp; node < lim; node += 2) {
        float acc = bv;
#pragma unroll
        for (int c = 0; c < 16; c++) {
            float4 v = ts[node][c];
            acc = fmaf(w[4 * c + 0], v.x, acc);
            acc = fmaf(w[4 * c + 1], v.y, acc);
            acc = fmaf(w[4 * c + 2], v.z, acc);
            acc = fmaf(w[4 * c + 3], v.w, acc);
        }
        xo[(n0 + node) * 64 + o] = fmaxf(acc, 0.f);
    }
}

// ---------------- pooling + final MLP ----------------
__global__ void k_pool(const int* __restrict__ batch, int n) {
    int t = blockIdx.x * blockDim.x + threadIdx.x;
    if (t >= n * 64) return;
    int nn = t >> 6, d = t & 63;
    int g = batch[nn];
    atomicAdd(&g_pool[g * 64 + d], g_x1[t]);
    if (d == 0) atomicAdd(&g_cnt[g], 1.f);
}

__global__ void k_mlp(const float* __restrict__ w1, const float* __restrict__ b1,
                      const float* __restrict__ w2, const float* __restrict__ b2,
                      float* __restrict__ out) {
    __shared__ float gs[64][65];
    __shared__ float hs[64][65];
    int tid = threadIdx.x;
    for (int i = tid; i < GNUM * 64; i += 128) {
        int g = i >> 6;
        float c = fmaxf(g_cnt[g], 1.f);
        gs[g][i & 63] = g_pool[i] / c;
    }
    __syncthreads();
    for (int i = tid; i < GNUM * 64; i += 128) {
        int g = i >> 6, k = i & 63;
        float acc = b1[k];
#pragma unroll
        for (int d = 0; d < 64; d++) acc = fmaf(gs[g][d], w1[k * 64 + d], acc);
        hs[g][k] = fmaxf(acc, 0.f);
    }
    __syncthreads();
    for (int i = tid; i < GNUM * 16; i += 128) {
        int g = i >> 4, k = i & 15;
        float acc = b2[k];
#pragma unroll
        for (int d = 0; d < 64; d++) acc = fmaf(hs[g][d], w2[k * 64 + d], acc);
        out[i] = acc;
    }
}

// ---------------- launch ----------------
extern "C" void kernel_launch(void* const* d_in, const int* in_sizes, int n_in,
                              void* d_out, int out_size) {
    const float* x      = (const float*)d_in[0];
    const int*   ei     = (const int*)d_in[1];
    const int*   batch  = (const int*)d_in[2];
    const float* pre_w  = (const float*)d_in[3];
    const float* pre_b  = (const float*)d_in[4];
    const float* post_w = (const float*)d_in[5];
    const float* post_b = (const float*)d_in[6];
    const float* lin_w  = (const float*)d_in[7];
    const float* lin_b  = (const float*)d_in[8];
    const float* mlp_w1 = (const float*)d_in[9];
    const float* mlp_b1 = (const float*)d_in[10];
    const float* mlp_w2 = (const float*)d_in[11];
    const float* mlp_b2 = (const float*)d_in[12];
    float* out = (float*)d_out;

    int N = in_sizes[0] / 64;
    int E = in_sizes[1] / 2;
    if (N > NMAX) N = NMAX;
    if (E > EMAX) E = EMAX;

    int nb = (N + 1023) / 1024;

    k_zero<<<(N + 255) / 256, 256>>>(N);
    k_deg<<<(E + 255) / 256, 256>>>(ei, E);
    k_scan1<<<nb, 1024>>>(N);
    k_scan2<<<1, 32>>>(nb);
    k_scan3<<<nb, 1024>>>(N);
    k_csr<<<(E + 255) / 256, 256>>>(ei, E);
    k_stat<<<(N + 255) / 256, 256>>>(N);

    int gpre = (N + 31) / 32;
    int gpost = (N + 127) / 128;
    int gagg = (N * 32 + 255) / 256;

    for (int l = 0; l < 3; l++) {
        int insel = (l == 0) ? 0 : ((l == 1) ? 1 : 2);
        int outsel = (l == 1) ? 2 : 1;
        k_pre<<<gpre, 128>>>(insel, x, pre_w + l * 64 * 128, pre_b + l * 64, N);
        k_aggr<<<gagg, 256>>>(N);
        k_post<<<gpost, 256>>>(insel, x, post_w + l * 64 * 832, post_b + l * 64, N);
        k_lin<<<gpre, 128>>>(lin_w + l * 64 * 64, lin_b + l * 64, outsel, N);
    }

    k_pool<<<(N * 64 + 255) / 256, 256>>>(batch, N);
    k_mlp<<<1, 128>>>(mlp_w1, mlp_b1, mlp_w2, mlp_b2, out);
}